// round 3
// baseline (speedup 1.0000x reference)
#include <cuda_runtime.h>
#include <math.h>

#define BB 32
#define GG 36
#define AA 5
#define TT 32
#define NCELL (BB*GG*GG*AA)       /* 207360 */
#define NFLOAT (NCELL*5)          /* 1036800 */
#define NVEC (NFLOAT/4)           /* 259200  */
#define IMGSZ 288.0f

#define NBLK 592
#define NTHR 256
#define TOTTHR (NBLK*NTHR)        /* 151552 */

// acc: 0=conf2_all, 1=conf2_obj, 2=conf1_obj, 3=loc_sum, 4=nme_sum
__device__ double d_acc[5];
__device__ int    d_done;
__device__ int    d_flag;         // obj list ready
__device__ int    d_count;
__device__ int    d_obj_cell[BB*TT];
__device__ int    d_obj_bt[BB*TT];

__device__ __forceinline__ int ld_acquire(int* p) {
    int v;
    asm volatile("ld.acquire.gpu.b32 %0, [%1];" : "=r"(v) : "l"(p) : "memory");
    return v;
}
__device__ __forceinline__ void st_release(int* p, int v) {
    asm volatile("st.release.gpu.b32 [%0], %1;" :: "l"(p), "r"(v) : "memory");
}

__device__ __forceinline__ float smooth_l1(float d) {
    float ad = fabsf(d);
    return (ad < 1.0f) ? 0.5f * d * d : ad - 0.5f;
}

__global__ void __launch_bounds__(NTHR)
fused_kernel(const float* __restrict__ bp,
             const float* __restrict__ lmp,
             const float* __restrict__ bt,
             const float* __restrict__ lmt,
             float* __restrict__ out) {
    int lane  = threadIdx.x & 31;
    int wid   = threadIdx.x >> 5;
    int tid   = blockIdx.x * NTHR + threadIdx.x;
    int gwarp = tid >> 5;

    double v0 = 0.0, v1 = 0.0, v2 = 0.0, v3 = 0.0, v4 = 0.0;

    // =====================================================================
    // Block 0: build compact obj list (last-t-wins dedupe), publish flag.
    // =====================================================================
    if (blockIdx.x == 0) {
        __shared__ int cells[BB * TT];
        __shared__ int s_cnt;
        if (threadIdx.x == 0) s_cnt = 0;
        __syncthreads();

#pragma unroll
        for (int u = 0; u < 4; u++) {
            int i = threadIdx.x + u * NTHR;          // i = b*TT + t
            const float* r = bt + (size_t)i * 5;
            float x = r[0], y = r[1], w = r[2], h = r[3], c4 = r[4];
            bool valid = (x + y + w + h + c4) != 0.0f;
            int gi = (int)(x * (float)GG);
            int gj = (int)(y * (float)GG);

            int cell = -1;
            if (valid && gi >= 0 && gi < GG && gj >= 0 && gj < GG) {
                float gx1 = (x - w * 0.5f) * IMGSZ;
                float gx2 = (x + w * 0.5f) * IMGSZ;
                float gy1 = (y - h * 0.5f) * IMGSZ;
                float gy2 = (y + h * 0.5f) * IMGSZ;
                float area_g = (gx2 - gx1 + 1.0f) * (gy2 - gy1 + 1.0f);

                float acx = (0.5f + (float)gi) / (float)GG;
                float acy = (0.5f + (float)gj) / (float)GG;

                const float aw[AA] = {0.24f, 0.12f, 0.08f, 0.28f, 0.15f};
                int best = 0;
                float best_iou = -1e30f;
#pragma unroll
                for (int a = 0; a < AA; a++) {
                    float ax1 = (acx - aw[a] * 0.5f) * IMGSZ;
                    float ax2 = (acx + aw[a] * 0.5f) * IMGSZ;
                    float ay1 = (acy - aw[a] * 0.5f) * IMGSZ;
                    float ay2 = (acy + aw[a] * 0.5f) * IMGSZ;
                    float ix1 = fmaxf(gx1, ax1);
                    float iy1 = fmaxf(gy1, ay1);
                    float ix2 = fminf(gx2, ax2);
                    float iy2 = fminf(gy2, ay2);
                    float inter  = (ix2 - ix1 + 1.0f) * (iy2 - iy1 + 1.0f);
                    float area_a = (ax2 - ax1 + 1.0f) * (ay2 - ay1 + 1.0f);
                    float iou = inter / (area_g + area_a - inter + 1e-16f);
                    if (iou > best_iou) { best_iou = iou; best = a; }
                }
                int b = i / TT;
                cell = ((b * GG + gj) * GG + gi) * AA + best;
            }
            cells[i] = cell;
        }
        __syncthreads();

#pragma unroll
        for (int u = 0; u < 4; u++) {
            int i = threadIdx.x + u * NTHR;
            int cell = cells[i];
            if (cell >= 0) {
                int b = i / TT, t = i % TT;
                bool win = true;
                for (int tp = t + 1; tp < TT; tp++)
                    if (cells[b * TT + tp] == cell) { win = false; break; }
                if (win) {
                    int idx = atomicAdd(&s_cnt, 1);
                    d_obj_cell[idx] = cell;
                    d_obj_bt[idx]   = i;
                }
            }
        }
        __syncthreads();
        if (threadIdx.x == 0) {
            d_count = s_cnt;
            __threadfence();
            st_release(&d_flag, 1);
        }
    }

    // =====================================================================
    // All blocks: conf^2 streaming pass (coalesced float4, 2 per thread).
    // =====================================================================
    const float4* bp4 = (const float4*)bp;
    {
        float4 va = bp4[tid];
        int i2 = tid + TOTTHR;
        bool has2 = (i2 < NVEC);
        float4 vb = has2 ? bp4[i2] : make_float4(0.f, 0.f, 0.f, 0.f);

        int rem = (4 * tid) % 5;
        if (rem != 0) {
            float vv[4] = {va.x, va.y, va.z, va.w};
            float c = vv[4 - rem];
            v0 += (double)c * (double)c;
        }
        if (has2) {
            int rem2 = (4 * i2) % 5;
            if (rem2 != 0) {
                float vv[4] = {vb.x, vb.y, vb.z, vb.w};
                float c = vv[4 - rem2];
                v0 += (double)c * (double)c;
            }
        }
    }

    // =====================================================================
    // Wait for obj list, then one warp per obj item.
    // =====================================================================
    int count;
    if (lane == 0) {
        while (ld_acquire(&d_flag) == 0) {}
        count = d_count;
    }
    count = __shfl_sync(0xffffffffu, count, 0);

    const int NWARP = TOTTHR / 32;
    for (int item = gwarp; item < count; item += NWARP) {
        int cell = d_obj_cell[item];
        int btid = d_obj_bt[item];

        const float2* lt = (const float2*)(lmt + (size_t)btid * 136);
        const float2* lp = (const float2*)(lmp + (size_t)cell * 136);
        float s = 0.0f;
#pragma unroll
        for (int u = 0; u < 3; u++) {
            int k = lane + u * 32;
            if (k < 68) {
                float2 a = lt[k];
                float2 p = lp[k];
                float dx = a.x - p.x;
                float dy = a.y - p.y;
                s += sqrtf(dx * dx + dy * dy);
            }
        }
#pragma unroll
        for (int o = 16; o > 0; o >>= 1)
            s += __shfl_down_sync(0xffffffffu, s, o);

        if (lane == 0) {
            const float* r = bt + (size_t)btid * 5;
            float l0 = log1pf(r[0]);
            float l1 = log1pf(r[1]);
            float l2 = log1pf(r[2]);
            float l3 = log1pf(r[3]);

            const float* p = bp + (size_t)cell * 5;
            float loc = smooth_l1(p[0] - l0) + smooth_l1(p[1] - l1)
                      + smooth_l1(p[2] - l2) + smooth_l1(p[3] - l3);
            v3 += (double)loc;

            float conf = p[4];
            v1 += (double)conf * (double)conf;
            float cm1 = conf - 1.0f;
            v2 += (double)cm1 * (double)cm1;

            float nf = sqrtf(l2 * l3);
            v4 += (double)(s / nf);
        }
    }

    // =====================================================================
    // Block reduction + global accumulate + last-block finalize & reset.
    // =====================================================================
    double vals[5] = {v0, v1, v2, v3, v4};
    __shared__ double sh[5][8];
#pragma unroll
    for (int j = 0; j < 5; j++) {
        double x = vals[j];
        for (int o = 16; o > 0; o >>= 1)
            x += __shfl_down_sync(0xffffffffu, x, o);
        if (lane == 0) sh[j][wid] = x;
    }
    __syncthreads();
    if (threadIdx.x == 0) {
#pragma unroll
        for (int j = 0; j < 5; j++) {
            double x = sh[j][0];
            for (int k = 1; k < 8; k++) x += sh[j][k];
            if (x != 0.0) atomicAdd(&d_acc[j], x);
        }
        __threadfence();
        int ticket = atomicAdd(&d_done, 1);
        if (ticket == gridDim.x - 1) {
            __threadfence();
            double conf2_all = d_acc[0];
            double conf2_obj = d_acc[1];
            double conf1_obj = d_acc[2];
            double loc_sum   = d_acc[3];
            double nme_sum   = d_acc[4];
            double cnt       = (double)d_count;

            double n_obj   = fmax(cnt, 1.0);
            double n_noobj = fmax((double)NCELL - cnt, 1.0);

            out[0] = (float)(2.0 * nme_sum / (68.0 * n_obj));
            out[1] = (float)(5.0 * loc_sum / (n_obj * 4.0));
            out[2] = (float)(0.5 * (conf2_all - conf2_obj) / n_noobj
                             + conf1_obj / n_obj);

            // reset state for next graph replay
#pragma unroll
            for (int j = 0; j < 5; j++) d_acc[j] = 0.0;
            d_done = 0;
            __threadfence();
            st_release(&d_flag, 0);
        }
    }
}

extern "C" void kernel_launch(void* const* d_in, const int* in_sizes, int n_in,
                              void* d_out, int out_size) {
    const float* bbox_pred = (const float*)d_in[0];   // (32,36,36,5,5)
    const float* lm_pred   = (const float*)d_in[1];   // (32,36,36,5,68,2)
    const float* bbox_tgt  = (const float*)d_in[2];   // (32,32,5)
    const float* lm_tgt    = (const float*)d_in[3];   // (32,32,68,2)
    float* out = (float*)d_out;

    fused_kernel<<<NBLK, NTHR>>>(bbox_pred, lm_pred, bbox_tgt, lm_tgt, out);
}

// round 4
// speedup vs baseline: 1.1429x; 1.1429x over previous
#include <cuda_runtime.h>
#include <math.h>

#define BB 32
#define GG 36
#define AA 5
#define TT 32
#define NCELL (BB*GG*GG*AA)       /* 207360 */
#define NFLOAT (NCELL*5)          /* 1036800 */
#define NVEC (NFLOAT/4)           /* 259200  */
#define IMGSZ 288.0f

#define NBLK 888
#define NTHR 256
#define TOTTHR (NBLK*NTHR)        /* 227328 */

// acc: 0=conf2_all, 1=conf2_obj, 2=conf1_obj, 3=loc_sum, 4=nme_sum, 5=obj_count
__device__ double d_acc[6];
__device__ int    d_done;

__device__ __forceinline__ float smooth_l1(float d) {
    float ad = fabsf(d);
    return (ad < 1.0f) ? 0.5f * d * d : ad - 0.5f;
}

__global__ void __launch_bounds__(NTHR)
fused_kernel(const float* __restrict__ bp,
             const float* __restrict__ lmp,
             const float* __restrict__ bt,
             const float* __restrict__ lmt,
             float* __restrict__ out) {
    int lane = threadIdx.x & 31;
    int wid  = threadIdx.x >> 5;
    int tid  = blockIdx.x * NTHR + threadIdx.x;

    double v0 = 0.0, v1 = 0.0, v2 = 0.0, v3 = 0.0, v4 = 0.0, v5 = 0.0;

    // =====================================================================
    // Conf^2 streaming pass: ~1 coalesced float4 per thread, front-batched.
    // =====================================================================
    {
        const float4* bp4 = (const float4*)bp;
        float4 va = bp4[tid];                      // tid < 227328 < 259200
        int i2 = tid + TOTTHR;
        bool has2 = (i2 < NVEC);
        float4 vb;
        if (has2) vb = bp4[i2];

        int rem = (4 * tid) % 5;                   // conf at idx 4 (mod 5)
        if (rem != 0) {
            float vv[4] = {va.x, va.y, va.z, va.w};
            float c = vv[4 - rem];
            v0 += (double)c * (double)c;
        }
        if (has2) {
            int rem2 = (4 * i2) % 5;
            if (rem2 != 0) {
                float vv[4] = {vb.x, vb.y, vb.z, vb.w};
                float c = vv[4 - rem2];
                v0 += (double)c * (double)c;
            }
        }
    }

    // =====================================================================
    // Blocks 0..31: per-batch target build + dedupe + obj losses.
    // No inter-block dependency — block b owns batch b entirely.
    // =====================================================================
    if (blockIdx.x < BB) {
        int b = blockIdx.x;
        __shared__ int   s_cell[TT];
        __shared__ bool  s_win[TT];

        // Warp 0: lane t computes the target cell for (b, t)
        if (wid == 0) {
            int t = lane;
            const float* r = bt + (size_t)(b * TT + t) * 5;
            float x = r[0], y = r[1], w = r[2], h = r[3], c4 = r[4];
            bool valid = (x + y + w + h + c4) != 0.0f;
            int gi = (int)(x * (float)GG);
            int gj = (int)(y * (float)GG);

            int cell = -1;
            if (valid && gi >= 0 && gi < GG && gj >= 0 && gj < GG) {
                float gx1 = (x - w * 0.5f) * IMGSZ;
                float gx2 = (x + w * 0.5f) * IMGSZ;
                float gy1 = (y - h * 0.5f) * IMGSZ;
                float gy2 = (y + h * 0.5f) * IMGSZ;
                float area_g = (gx2 - gx1 + 1.0f) * (gy2 - gy1 + 1.0f);

                float acx = (0.5f + (float)gi) / (float)GG;
                float acy = (0.5f + (float)gj) / (float)GG;

                const float aw[AA] = {0.24f, 0.12f, 0.08f, 0.28f, 0.15f};
                int best = 0;
                float best_iou = -1e30f;
#pragma unroll
                for (int a = 0; a < AA; a++) {
                    float ax1 = (acx - aw[a] * 0.5f) * IMGSZ;
                    float ax2 = (acx + aw[a] * 0.5f) * IMGSZ;
                    float ay1 = (acy - aw[a] * 0.5f) * IMGSZ;
                    float ay2 = (acy + aw[a] * 0.5f) * IMGSZ;
                    float ix1 = fmaxf(gx1, ax1);
                    float iy1 = fmaxf(gy1, ay1);
                    float ix2 = fminf(gx2, ax2);
                    float iy2 = fminf(gy2, ay2);
                    float inter  = (ix2 - ix1 + 1.0f) * (iy2 - iy1 + 1.0f);
                    float area_a = (ax2 - ax1 + 1.0f) * (ay2 - ay1 + 1.0f);
                    float iou = inter / (area_g + area_a - inter + 1e-16f);
                    if (iou > best_iou) { best_iou = iou; best = a; }  // first-max
                }
                cell = ((b * GG + gj) * GG + gi) * AA + best;
            }
            s_cell[t] = cell;
        }
        __syncthreads();

        // All threads: dedupe flags (last t wins per cell)
        if (threadIdx.x < TT) {
            int t = threadIdx.x;
            int cell = s_cell[t];
            bool win = (cell >= 0);
            if (win) {
                for (int tp = t + 1; tp < TT; tp++)
                    if (s_cell[tp] == cell) { win = false; break; }
            }
            s_win[t] = win;
        }
        __syncthreads();

        // 8 warps: warp w handles t = w, w+8, w+16, w+24
#pragma unroll
        for (int u = 0; u < 4; u++) {
            int t = wid + u * 8;
            if (!s_win[t]) continue;
            int cell = s_cell[t];
            int btid = b * TT + t;

            const float2* lt = (const float2*)(lmt + (size_t)btid * 136);
            const float2* lp = (const float2*)(lmp + (size_t)cell * 136);
            float s = 0.0f;
#pragma unroll
            for (int uu = 0; uu < 3; uu++) {
                int k = lane + uu * 32;
                if (k < 68) {
                    float2 a = lt[k];
                    float2 p = lp[k];
                    float dx = a.x - p.x;
                    float dy = a.y - p.y;
                    s += sqrtf(dx * dx + dy * dy);
                }
            }
#pragma unroll
            for (int o = 16; o > 0; o >>= 1)
                s += __shfl_down_sync(0xffffffffu, s, o);

            if (lane == 0) {
                const float* r = bt + (size_t)btid * 5;
                float l0 = log1pf(r[0]);
                float l1 = log1pf(r[1]);
                float l2 = log1pf(r[2]);
                float l3 = log1pf(r[3]);

                const float* p = bp + (size_t)cell * 5;
                float loc = smooth_l1(p[0] - l0) + smooth_l1(p[1] - l1)
                          + smooth_l1(p[2] - l2) + smooth_l1(p[3] - l3);
                v3 += (double)loc;

                float conf = p[4];
                v1 += (double)conf * (double)conf;
                float cm1 = conf - 1.0f;
                v2 += (double)cm1 * (double)cm1;

                float nf = sqrtf(l2 * l3);
                v4 += (double)(s / nf);
                v5 += 1.0;
            }
        }
    }

    // =====================================================================
    // Block reduction (6 doubles) + global atomics + last-block finalize.
    // =====================================================================
    double vals[6] = {v0, v1, v2, v3, v4, v5};
    __shared__ double sh[6][8];
#pragma unroll
    for (int j = 0; j < 6; j++) {
        double x = vals[j];
        for (int o = 16; o > 0; o >>= 1)
            x += __shfl_down_sync(0xffffffffu, x, o);
        if (lane == 0) sh[j][wid] = x;
    }
    __syncthreads();
    if (threadIdx.x == 0) {
#pragma unroll
        for (int j = 0; j < 6; j++) {
            double x = sh[j][0];
            for (int k = 1; k < 8; k++) x += sh[j][k];
            if (x != 0.0) atomicAdd(&d_acc[j], x);
        }
        __threadfence();
        int ticket = atomicAdd(&d_done, 1);
        if (ticket == NBLK - 1) {
            __threadfence();
            double conf2_all = d_acc[0];
            double conf2_obj = d_acc[1];
            double conf1_obj = d_acc[2];
            double loc_sum   = d_acc[3];
            double nme_sum   = d_acc[4];
            double cnt       = d_acc[5];

            double n_obj   = fmax(cnt, 1.0);
            double n_noobj = fmax((double)NCELL - cnt, 1.0);

            out[0] = (float)(2.0 * nme_sum / (68.0 * n_obj));
            out[1] = (float)(5.0 * loc_sum / (n_obj * 4.0));
            out[2] = (float)(0.5 * (conf2_all - conf2_obj) / n_noobj
                             + conf1_obj / n_obj);

            // reset for next graph replay
#pragma unroll
            for (int j = 0; j < 6; j++) d_acc[j] = 0.0;
            __threadfence();
            d_done = 0;
        }
    }
}

extern "C" void kernel_launch(void* const* d_in, const int* in_sizes, int n_in,
                              void* d_out, int out_size) {
    const float* bbox_pred = (const float*)d_in[0];   // (32,36,36,5,5)
    const float* lm_pred   = (const float*)d_in[1];   // (32,36,36,5,68,2)
    const float* bbox_tgt  = (const float*)d_in[2];   // (32,32,5)
    const float* lm_tgt    = (const float*)d_in[3];   // (32,32,68,2)
    float* out = (float*)d_out;

    fused_kernel<<<NBLK, NTHR>>>(bbox_pred, lm_pred, bbox_tgt, lm_tgt, out);
}

// round 5
// speedup vs baseline: 1.3316x; 1.1652x over previous
#include <cuda_runtime.h>
#include <math.h>

#define BB 32
#define GG 36
#define AA 5
#define TT 32
#define NCELL (BB*GG*GG*AA)       /* 207360 */
#define NFLOAT (NCELL*5)          /* 1036800 */
#define NVEC (NFLOAT/4)           /* 259200  */
#define IMGSZ 288.0f

#define NBLK 148
#define NTHR 512
#define NW   (NTHR/32)            /* 16 warps/block */
#define TOT  (NBLK*NTHR)          /* 75776 */
#define NTGT (BB*TT)              /* 1024 */
#define SETUP_BLOCKS (NTGT/NW)    /* 64 blocks own obj slots */

// acc: 0=conf2_all, 1=conf2_obj, 2=conf1_obj, 3=loc_sum, 4=nme_sum, 5=obj_count
__device__ double d_acc[6];
__device__ int    d_done;

__device__ __forceinline__ float smooth_l1(float d) {
    float ad = fabsf(d);
    return (ad < 1.0f) ? 0.5f * d * d : ad - 0.5f;
}

__device__ __forceinline__ int compute_cell(int i, const float* __restrict__ bt) {
    const float* r = bt + (size_t)i * 5;
    float x = r[0], y = r[1], w = r[2], h = r[3], c4 = r[4];
    bool valid = (x + y + w + h + c4) != 0.0f;
    int gi = (int)(x * (float)GG);
    int gj = (int)(y * (float)GG);
    if (!valid || gi < 0 || gi >= GG || gj < 0 || gj >= GG) return -1;

    float gx1 = (x - w * 0.5f) * IMGSZ;
    float gx2 = (x + w * 0.5f) * IMGSZ;
    float gy1 = (y - h * 0.5f) * IMGSZ;
    float gy2 = (y + h * 0.5f) * IMGSZ;
    float area_g = (gx2 - gx1 + 1.0f) * (gy2 - gy1 + 1.0f);

    float acx = (0.5f + (float)gi) / (float)GG;
    float acy = (0.5f + (float)gj) / (float)GG;

    const float aw[AA] = {0.24f, 0.12f, 0.08f, 0.28f, 0.15f};
    int best = 0;
    float best_iou = -1e30f;
#pragma unroll
    for (int a = 0; a < AA; a++) {
        float ax1 = (acx - aw[a] * 0.5f) * IMGSZ;
        float ax2 = (acx + aw[a] * 0.5f) * IMGSZ;
        float ay1 = (acy - aw[a] * 0.5f) * IMGSZ;
        float ay2 = (acy + aw[a] * 0.5f) * IMGSZ;
        float ix1 = fmaxf(gx1, ax1);
        float iy1 = fmaxf(gy1, ay1);
        float ix2 = fminf(gx2, ax2);
        float iy2 = fminf(gy2, ay2);
        float inter  = (ix2 - ix1 + 1.0f) * (iy2 - iy1 + 1.0f);
        float area_a = (ax2 - ax1 + 1.0f) * (ay2 - ay1 + 1.0f);
        float iou = inter / (area_g + area_a - inter + 1e-16f);
        if (iou > best_iou) { best_iou = iou; best = a; }   // first-max argmax
    }
    int b = i / TT;
    return ((b * GG + gj) * GG + gi) * AA + best;
}

__global__ void __launch_bounds__(NTHR)
fused_kernel(const float* __restrict__ bp,
             const float* __restrict__ lmp,
             const float* __restrict__ bt,
             const float* __restrict__ lmt,
             float* __restrict__ out) {
    int lane = threadIdx.x & 31;
    int wid  = threadIdx.x >> 5;
    int tid  = blockIdx.x * NTHR + threadIdx.x;

    __shared__ int  s_cell[NTGT];
    __shared__ char s_win[NTGT];

    double v0 = 0.0, v1 = 0.0, v2 = 0.0, v3 = 0.0, v4 = 0.0, v5 = 0.0;

    // ---- issue conf loads first (front-batched, MLP=4) ----
    const float4* bp4 = (const float4*)bp;
    float4 va = bp4[tid];                 // tid        < 75776  < 259200
    float4 vb = bp4[tid + TOT];           // +75776     < 151552
    float4 vc = bp4[tid + 2 * TOT];       // +151552    < 227328
    int i3 = tid + 3 * TOT;
    bool has4 = (i3 < NVEC);
    float4 vd;
    if (has4) vd = bp4[i3];

    // ---- blocks 0..63: replicated setup (cell table + last-t-wins flags) ----
    bool setup_blk = (blockIdx.x < SETUP_BLOCKS);
    if (setup_blk) {
        int i0 = threadIdx.x;
        int i1 = threadIdx.x + NTHR;
        s_cell[i0] = compute_cell(i0, bt);
        s_cell[i1] = compute_cell(i1, bt);
        __syncthreads();
#pragma unroll
        for (int u = 0; u < 2; u++) {
            int i = threadIdx.x + u * NTHR;
            int t = i & (TT - 1);
            int cell = s_cell[i];
            bool win = (cell >= 0);
            if (win) {
                int base = i - t;
                for (int tp = t + 1; tp < TT; tp++)
                    if (s_cell[base + tp] == cell) { win = false; break; }
            }
            s_win[i] = win ? 1 : 0;
        }
        __syncthreads();
    }

    // ---- conf^2 accumulation ----
    {
        int rem = (4 * tid) % 5;          // conf sits at index 4 (mod 5)
        if (rem != 0) {
            float vv[4] = {va.x, va.y, va.z, va.w};
            float c = vv[4 - rem];
            v0 += (double)c * (double)c;
        }
        int rem1 = (4 * (tid + TOT)) % 5;
        if (rem1 != 0) {
            float vv[4] = {vb.x, vb.y, vb.z, vb.w};
            float c = vv[4 - rem1];
            v0 += (double)c * (double)c;
        }
        int rem2 = (4 * (tid + 2 * TOT)) % 5;
        if (rem2 != 0) {
            float vv[4] = {vc.x, vc.y, vc.z, vc.w};
            float c = vv[4 - rem2];
            v0 += (double)c * (double)c;
        }
        if (has4) {
            int rem3 = (4 * i3) % 5;
            if (rem3 != 0) {
                float vv[4] = {vd.x, vd.y, vd.z, vd.w};
                float c = vv[4 - rem3];
                v0 += (double)c * (double)c;
            }
        }
    }

    // ---- obj phase: global warp g owns target slot g (one item max) ----
    if (setup_blk) {
        int g = blockIdx.x * NW + wid;    // g < 1024
        if (s_win[g]) {
            int cell = s_cell[g];

            const float2* lt = (const float2*)(lmt + (size_t)g * 136);
            const float2* lp = (const float2*)(lmp + (size_t)cell * 136);
            float s = 0.0f;
            {
                float2 a0 = lt[lane],      p0 = lp[lane];
                float2 a1 = lt[lane + 32], p1 = lp[lane + 32];
                float dx0 = a0.x - p0.x, dy0 = a0.y - p0.y;
                float dx1 = a1.x - p1.x, dy1 = a1.y - p1.y;
                s = sqrtf(dx0 * dx0 + dy0 * dy0) + sqrtf(dx1 * dx1 + dy1 * dy1);
                if (lane < 4) {
                    float2 a2 = lt[lane + 64], p2 = lp[lane + 64];
                    float dx2 = a2.x - p2.x, dy2 = a2.y - p2.y;
                    s += sqrtf(dx2 * dx2 + dy2 * dy2);
                }
            }
#pragma unroll
            for (int o = 16; o > 0; o >>= 1)
                s += __shfl_down_sync(0xffffffffu, s, o);

            if (lane == 0) {
                const float* r = bt + (size_t)g * 5;
                float l0 = log1pf(r[0]);
                float l1 = log1pf(r[1]);
                float l2 = log1pf(r[2]);
                float l3 = log1pf(r[3]);

                const float* p = bp + (size_t)cell * 5;
                float loc = smooth_l1(p[0] - l0) + smooth_l1(p[1] - l1)
                          + smooth_l1(p[2] - l2) + smooth_l1(p[3] - l3);
                v3 = (double)loc;

                float conf = p[4];
                v1 = (double)conf * (double)conf;
                float cm1 = conf - 1.0f;
                v2 = (double)cm1 * (double)cm1;

                float nf = sqrtf(l2 * l3);
                v4 = (double)(s / nf);
                v5 = 1.0;
            }
        }
    }

    // ---- block reduction (6 doubles, 16 warps) + atomics + finalize ----
    double vals[6] = {v0, v1, v2, v3, v4, v5};
    __shared__ double sh[6][NW];
#pragma unroll
    for (int j = 0; j < 6; j++) {
        double x = vals[j];
        for (int o = 16; o > 0; o >>= 1)
            x += __shfl_down_sync(0xffffffffu, x, o);
        if (lane == 0) sh[j][wid] = x;
    }
    __syncthreads();
    if (threadIdx.x == 0) {
#pragma unroll
        for (int j = 0; j < 6; j++) {
            double x = sh[j][0];
#pragma unroll
            for (int k = 1; k < NW; k++) x += sh[j][k];
            if (x != 0.0) atomicAdd(&d_acc[j], x);
        }
        __threadfence();
        int ticket = atomicAdd(&d_done, 1);
        if (ticket == NBLK - 1) {
            __threadfence();
            double conf2_all = d_acc[0];
            double conf2_obj = d_acc[1];
            double conf1_obj = d_acc[2];
            double loc_sum   = d_acc[3];
            double nme_sum   = d_acc[4];
            double cnt       = d_acc[5];

            double n_obj   = fmax(cnt, 1.0);
            double n_noobj = fmax((double)NCELL - cnt, 1.0);

            out[0] = (float)(2.0 * nme_sum / (68.0 * n_obj));
            out[1] = (float)(5.0 * loc_sum / (n_obj * 4.0));
            out[2] = (float)(0.5 * (conf2_all - conf2_obj) / n_noobj
                             + conf1_obj / n_obj);

            // reset for next graph replay
#pragma unroll
            for (int j = 0; j < 6; j++) d_acc[j] = 0.0;
            __threadfence();
            d_done = 0;
        }
    }
}

extern "C" void kernel_launch(void* const* d_in, const int* in_sizes, int n_in,
                              void* d_out, int out_size) {
    const float* bbox_pred = (const float*)d_in[0];   // (32,36,36,5,5)
    const float* lm_pred   = (const float*)d_in[1];   // (32,36,36,5,68,2)
    const float* bbox_tgt  = (const float*)d_in[2];   // (32,32,5)
    const float* lm_tgt    = (const float*)d_in[3];   // (32,32,68,2)
    float* out = (float*)d_out;

    fused_kernel<<<NBLK, NTHR>>>(bbox_pred, lm_pred, bbox_tgt, lm_tgt, out);
}

// round 6
// speedup vs baseline: 1.9439x; 1.4598x over previous
#include <cuda_runtime.h>
#include <math.h>

#define BB 32
#define GG 36
#define AA 5
#define TT 32
#define NCELL (BB*GG*GG*AA)       /* 207360 */
#define NVEC  (NCELL*5/4)         /* 259200 float4 */
#define IMGSZ 288.0f

#define NBLK 296
#define NTHR 256
#define TOT  (NBLK*NTHR)          /* 75776 */
#define SETUP_BLOCKS 128          /* 4 blocks per batch, 8 obj warps each */

// d_acc: 0=conf2_all, 1=conf2_obj, 2=conf1_obj, 3=loc_sum, 4=nme_sum
__device__ double d_acc[5];
__device__ int    d_cnt;
__device__ int    d_done;

__device__ __forceinline__ float smooth_l1(float d) {
    float ad = fabsf(d);
    return (ad < 1.0f) ? 0.5f * d * d : ad - 0.5f;
}

// conf element inside float4 #i sits at lane k=(i+4)%5 (k==4 -> none)
__device__ __forceinline__ float conf_sq(float4 v, int i) {
    int k = (i + 4) % 5;
    float c = (k == 0) ? v.x : (k == 1) ? v.y : (k == 2) ? v.z : (k == 3) ? v.w : 0.0f;
    return c * c;
}

__device__ __forceinline__ int compute_cell(int i, const float* __restrict__ bt) {
    const float* r = bt + (size_t)i * 5;
    float x = r[0], y = r[1], w = r[2], h = r[3], c4 = r[4];
    bool valid = (x + y + w + h + c4) != 0.0f;
    int gi = (int)(x * (float)GG);
    int gj = (int)(y * (float)GG);
    if (!valid || gi < 0 || gi >= GG || gj < 0 || gj >= GG) return -1;

    float gx1 = (x - w * 0.5f) * IMGSZ;
    float gx2 = (x + w * 0.5f) * IMGSZ;
    float gy1 = (y - h * 0.5f) * IMGSZ;
    float gy2 = (y + h * 0.5f) * IMGSZ;
    float area_g = (gx2 - gx1 + 1.0f) * (gy2 - gy1 + 1.0f);

    float acx = (0.5f + (float)gi) / (float)GG;
    float acy = (0.5f + (float)gj) / (float)GG;

    const float aw[AA] = {0.24f, 0.12f, 0.08f, 0.28f, 0.15f};
    int best = 0;
    float best_iou = -1e30f;
#pragma unroll
    for (int a = 0; a < AA; a++) {
        float ax1 = (acx - aw[a] * 0.5f) * IMGSZ;
        float ax2 = (acx + aw[a] * 0.5f) * IMGSZ;
        float ay1 = (acy - aw[a] * 0.5f) * IMGSZ;
        float ay2 = (acy + aw[a] * 0.5f) * IMGSZ;
        float ix1 = fmaxf(gx1, ax1);
        float iy1 = fmaxf(gy1, ay1);
        float ix2 = fminf(gx2, ax2);
        float iy2 = fminf(gy2, ay2);
        float inter  = (ix2 - ix1 + 1.0f) * (iy2 - iy1 + 1.0f);
        float area_a = (ax2 - ax1 + 1.0f) * (ay2 - ay1 + 1.0f);
        float iou = inter / (area_g + area_a - inter + 1e-16f);
        if (iou > best_iou) { best_iou = iou; best = a; }   // first-max argmax
    }
    int b = i / TT;
    return ((b * GG + gj) * GG + gi) * AA + best;
}

__global__ void __launch_bounds__(NTHR)
fused_kernel(const float* __restrict__ bp,
             const float* __restrict__ lmp,
             const float* __restrict__ bt,
             const float* __restrict__ lmt,
             float* __restrict__ out) {
    int lane = threadIdx.x & 31;
    int wid  = threadIdx.x >> 5;
    int tid  = blockIdx.x * NTHR + threadIdx.x;

    __shared__ int      s_cell[TT];
    __shared__ unsigned s_winmask;

    // ---- issue all conf loads first (independent, MLP up to 4) ----
    const float4* bp4 = (const float4*)bp;
    float4 va = bp4[tid];                  //  < 75776
    float4 vb = bp4[tid + TOT];            //  < 151552
    float4 vc = bp4[tid + 2 * TOT];        //  < 227328  (< 259200 ok)
    int i3 = tid + 3 * TOT;
    bool has4 = (i3 < NVEC);
    float4 vd;
    if (has4) vd = bp4[i3];

    // ---- setup: block s<128 handles batch b = s>>2; warp 0 builds cells ----
    bool setup_blk = (blockIdx.x < SETUP_BLOCKS);
    int b = blockIdx.x >> 2;
    int q = blockIdx.x & 3;
    if (setup_blk && wid == 0) {
        int cell = compute_cell(b * TT + lane, bt);     // lane == t
        s_cell[lane] = cell;
        unsigned m = __match_any_sync(0xffffffffu, cell);
        bool win = (cell >= 0) && ((31 - __clz(m)) == lane);  // last t wins
        unsigned wm = __ballot_sync(0xffffffffu, win);
        if (lane == 0) s_winmask = wm;
    }

    // ---- conf^2 (branchless selects, fp32 partial then double) ----
    float cs = conf_sq(va, tid)
             + conf_sq(vb, tid + TOT)
             + conf_sq(vc, tid + 2 * TOT);
    if (has4) cs += conf_sq(vd, i3);
    double v0 = (double)cs;

    if (setup_blk) {
        __syncthreads();

        // ---- obj phase: warp `wid` owns target t = q*8 + wid (one item) ----
        unsigned wm = s_winmask;
        int t = q * 8 + wid;
        if ((wm >> t) & 1u) {
            int cell = s_cell[t];
            int btid = b * TT + t;

            // all loads issued up front (one round trip)
            const float2* lt = (const float2*)(lmt + (size_t)btid * 136);
            const float2* lp = (const float2*)(lmp + (size_t)cell * 136);
            float2 a0 = lt[lane],      p0 = lp[lane];
            float2 a1 = lt[lane + 32], p1 = lp[lane + 32];
            float2 a2, p2;
            bool extra = (lane < 4);
            if (extra) { a2 = lt[lane + 64]; p2 = lp[lane + 64]; }

            float r0, r1, r2, r3, pb0, pb1, pb2, pb3, pb4;
            if (lane == 0) {
                const float* r = bt + (size_t)btid * 5;
                r0 = r[0]; r1 = r[1]; r2 = r[2]; r3 = r[3];
                const float* p = bp + (size_t)cell * 5;
                pb0 = p[0]; pb1 = p[1]; pb2 = p[2]; pb3 = p[3]; pb4 = p[4];
            }

            float dx0 = a0.x - p0.x, dy0 = a0.y - p0.y;
            float dx1 = a1.x - p1.x, dy1 = a1.y - p1.y;
            float s = sqrtf(dx0 * dx0 + dy0 * dy0) + sqrtf(dx1 * dx1 + dy1 * dy1);
            if (extra) {
                float dx2 = a2.x - p2.x, dy2 = a2.y - p2.y;
                s += sqrtf(dx2 * dx2 + dy2 * dy2);
            }
#pragma unroll
            for (int o = 16; o > 0; o >>= 1)
                s += __shfl_down_sync(0xffffffffu, s, o);

            if (lane == 0) {
                float l0 = log1pf(r0);
                float l1 = log1pf(r1);
                float l2 = log1pf(r2);
                float l3 = log1pf(r3);

                float loc = smooth_l1(pb0 - l0) + smooth_l1(pb1 - l1)
                          + smooth_l1(pb2 - l2) + smooth_l1(pb3 - l3);
                float cm1 = pb4 - 1.0f;
                float nf  = sqrtf(l2 * l3);

                atomicAdd(&d_acc[1], (double)pb4 * (double)pb4);
                atomicAdd(&d_acc[2], (double)cm1 * (double)cm1);
                atomicAdd(&d_acc[3], (double)loc);
                atomicAdd(&d_acc[4], (double)(s / nf));
                atomicAdd(&d_cnt, 1);
                __threadfence();
            }
        }
    }

    // ---- tail: block-reduce only conf2_all, atomic, ticket finalize ----
    {
        double x = v0;
#pragma unroll
        for (int o = 16; o > 0; o >>= 1)
            x += __shfl_down_sync(0xffffffffu, x, o);
        __shared__ double sh[NTHR / 32];
        if (lane == 0) sh[wid] = x;
        __syncthreads();
        if (threadIdx.x == 0) {
            double sum = sh[0];
#pragma unroll
            for (int k = 1; k < NTHR / 32; k++) sum += sh[k];
            atomicAdd(&d_acc[0], sum);
            __threadfence();
            int ticket = atomicAdd(&d_done, 1);
            if (ticket == NBLK - 1) {
                __threadfence();
                double conf2_all = d_acc[0];
                double conf2_obj = d_acc[1];
                double conf1_obj = d_acc[2];
                double loc_sum   = d_acc[3];
                double nme_sum   = d_acc[4];
                double cnt       = (double)d_cnt;

                double n_obj   = fmax(cnt, 1.0);
                double n_noobj = fmax((double)NCELL - cnt, 1.0);

                out[0] = (float)(2.0 * nme_sum / (68.0 * n_obj));
                out[1] = (float)(5.0 * loc_sum / (n_obj * 4.0));
                out[2] = (float)(0.5 * (conf2_all - conf2_obj) / n_noobj
                                 + conf1_obj / n_obj);

                // reset for next graph replay
#pragma unroll
                for (int j = 0; j < 5; j++) d_acc[j] = 0.0;
                d_cnt = 0;
                __threadfence();
                d_done = 0;
            }
        }
    }
}

extern "C" void kernel_launch(void* const* d_in, const int* in_sizes, int n_in,
                              void* d_out, int out_size) {
    const float* bbox_pred = (const float*)d_in[0];   // (32,36,36,5,5)
    const float* lm_pred   = (const float*)d_in[1];   // (32,36,36,5,68,2)
    const float* bbox_tgt  = (const float*)d_in[2];   // (32,32,5)
    const float* lm_tgt    = (const float*)d_in[3];   // (32,32,68,2)
    float* out = (float*)d_out;

    fused_kernel<<<NBLK, NTHR>>>(bbox_pred, lm_pred, bbox_tgt, lm_tgt, out);
}